// round 16
// baseline (speedup 1.0000x reference)
#include <cuda_runtime.h>
#include <cuda_bf16.h>
#include <cuda_fp16.h>
#include <math.h>
#include <stdint.h>

#define S_LEN   2048
#define BATCH   2
#define D_MODEL 2048
#define KV_DIM  512
#define NH      32
#define NKV     8
#define HD      64
#define ROWS    (BATCH*S_LEN)   // 4096
#define NQKV    (D_MODEL + 2*KV_DIM)   // 3072
#define NALLW   (NQKV + D_MODEL)       // 5120

// ---------------- scratch (device globals; no allocation allowed) ----------
__device__ __half g_xh[ROWS*D_MODEL];        // x fp16 (later: O fp16)
__device__ __half g_whA[NQKV*D_MODEL];       // [wq;wk;wv]^T fp16
__device__ __half g_who[D_MODEL*D_MODEL];    // wo^T fp16
__device__ __half g_Qf[ROWS*D_MODEL];        // RoPE'd, 0.125*log2e-scaled fp16
__device__ __half g_Kh[ROWS*KV_DIM];         // RoPE'd K fp16 [token][kvdim]
__device__ __half g_Vh[ROWS*KV_DIM];         // V fp16 [token][kvdim]
__device__ float g_cos[S_LEN*32];
__device__ float g_sin[S_LEN*32];

// ======================= base-ISA PTX helpers ===============================
__device__ __forceinline__ uint32_t smem_u32(const void* p) {
    uint32_t a;
    asm("{ .reg .u64 t; cvta.to.shared.u64 t, %1; cvt.u32.u64 %0, t; }"
        : "=r"(a) : "l"(p));
    return a;
}
__device__ __forceinline__ void cpa16(uint32_t saddr, const void* g) {
    asm volatile("cp.async.cg.shared.global [%0], [%1], 16;" :: "r"(saddr), "l"(g));
}
#define CP_COMMIT() asm volatile("cp.async.commit_group;" ::: "memory")
#define CP_WAIT(n)  asm volatile("cp.async.wait_group %0;" :: "n"(n) : "memory")

#define LDSM_X4(r0, r1, r2, r3, a) \
    asm volatile("ldmatrix.sync.aligned.m8n8.x4.shared.b16 {%0,%1,%2,%3}, [%4];" \
        : "=r"(r0), "=r"(r1), "=r"(r2), "=r"(r3) : "r"(a))

#define LDSM_X4T(r0, r1, r2, r3, a) \
    asm volatile("ldmatrix.sync.aligned.m8n8.x4.trans.shared.b16 {%0,%1,%2,%3}, [%4];" \
        : "=r"(r0), "=r"(r1), "=r"(r2), "=r"(r3) : "r"(a))

#define MMA_FP16(d, a, b0, b1) \
    asm volatile("mma.sync.aligned.m16n8k16.row.col.f32.f16.f16.f32 " \
        "{%0,%1,%2,%3}, {%4,%5,%6,%7}, {%8,%9}, {%0,%1,%2,%3};" \
        : "+f"((d)[0]), "+f"((d)[1]), "+f"((d)[2]), "+f"((d)[3]) \
        : "r"((a)[0]), "r"((a)[1]), "r"((a)[2]), "r"((a)[3]), "r"(b0), "r"(b1))

#define PACK_HF2(d, lo, hi) \
    asm("cvt.rn.f16x2.f32 %0, %1, %2;" : "=r"(d) : "f"(hi), "f"(lo))

#define EX2_HF2(x) \
    asm("ex2.approx.f16x2 %0, %0;" : "+r"(x))

__device__ __forceinline__ __half2 uh2(uint32_t r) {
    __half2 h;
    *(uint32_t*)&h = r;
    return h;
}

// ======================= precompute kernels =================================
struct Freqs { float f[32]; };

__global__ void split_kernel(const float* __restrict__ a, int n4, Freqs fr)
{
    int i = blockIdx.x * blockDim.x + threadIdx.x;
    if (i < S_LEN * 32) {
        int s = i >> 5, p = i & 31;
        float ang = (float)s * fr.f[p];
        float c, sn;
        sincosf(ang, &sn, &c);
        g_cos[i] = c;
        g_sin[i] = sn;
    }
    if (i >= n4) return;
    float4 v = ((const float4*)a)[i];
    ((__half2*)g_xh)[2*i]   = __floats2half2_rn(v.x, v.y);
    ((__half2*)g_xh)[2*i+1] = __floats2half2_rn(v.z, v.w);
}

// ALL FOUR weights -> transposed fp16
__global__ void splitT_all(const float* __restrict__ wq,
                           const float* __restrict__ wk,
                           const float* __restrict__ wv,
                           const float* __restrict__ wo)
{
    __shared__ float t[32][33];
    int n0 = blockIdx.x * 32, k0 = blockIdx.y * 32;
    const float* w;
    int Nd, c0;
    __half* dst;
    int drow;
    if (n0 < D_MODEL)                 { w = wq; Nd = D_MODEL; c0 = n0;                    dst = g_whA; drow = n0; }
    else if (n0 < D_MODEL + KV_DIM)   { w = wk; Nd = KV_DIM;  c0 = n0 - D_MODEL;          dst = g_whA; drow = n0; }
    else if (n0 < NQKV)               { w = wv; Nd = KV_DIM;  c0 = n0 - D_MODEL - KV_DIM; dst = g_whA; drow = n0; }
    else                              { w = wo; Nd = D_MODEL; c0 = n0 - NQKV;             dst = g_who; drow = n0 - NQKV; }
    for (int r = threadIdx.y; r < 32; r += 8)
        t[r][threadIdx.x] = w[(size_t)(k0 + r) * Nd + c0 + threadIdx.x];
    __syncthreads();
    for (int r = threadIdx.y; r < 32; r += 8)
        dst[(size_t)(drow + r) * D_MODEL + k0 + threadIdx.x] =
            __float2half_rn(t[threadIdx.x][r]);
}

// ======================= fp16 mma.sync GEMM, BK=64, 3 CTAs/SM ===============
// 256 thr, 8 warps as 2m x 4n of 64x16. BM=128, BN=64.
#define BM 128
#define BN 64
#define BK 64
#define STAGES 3
#define A_TILE  (BM*BK*2)        // 16384 B
#define B_TILE  (BN*BK*2)        // 8192 B
#define STAGE_B (A_TILE + B_TILE)// 24576 B

template<int EPI>
__global__ __launch_bounds__(256, 3) void gemm_mma(
    const __half* __restrict__ Ah, const __half* __restrict__ Bh,
    float* __restrict__ C, int M, int N, int K)
{
    extern __shared__ char smem_raw[];
    const int tid  = threadIdx.x;
    const int wid  = tid >> 5;
    const int lane = tid & 31;
    const int m0 = blockIdx.y * BM, n0 = blockIdx.x * BN;
    const int wm = (wid >> 2) * 64;
    const int wn = (wid & 3) * 16;
    const int nk = K / BK;

    uint32_t raw = smem_u32(smem_raw);
    uint32_t st  = (raw + 1023u) & ~1023u;

    const __half* gA_h = Ah + (size_t)m0 * K;
    const __half* gB_h = Bh + (size_t)n0 * K;

    const int lr = tid >> 3, lc = tid & 7;   // lr: 0..31

    auto load_stage = [&](int s, int j) {
        uint32_t sb = st + s * STAGE_B;
        size_t kk = (size_t)j * BK;
        #pragma unroll
        for (int it = 0; it < 4; it++) {
            int r = lr + it * 32;
            uint32_t so = (uint32_t)(r * 128 + ((lc ^ (r & 7)) << 4));
            cpa16(sb + so, gA_h + kk + (size_t)r * K + lc * 8);
        }
        #pragma unroll
        for (int it = 0; it < 2; it++) {
            int r = lr + it * 32;
            uint32_t so = (uint32_t)(r * 128 + ((lc ^ (r & 7)) << 4));
            cpa16(sb + A_TILE + so, gB_h + kk + (size_t)r * K + lc * 8);
        }
    };

    float acc[4][2][4];
    #pragma unroll
    for (int i = 0; i < 4; i++)
        #pragma unroll
        for (int j = 0; j < 2; j++)
            #pragma unroll
            for (int k = 0; k < 4; k++) acc[i][j][k] = 0.f;

    const int arow = wm + (lane & 15);
    const int acol = (lane >> 4);
    const int brow = wn + (lane & 7) + ((lane >> 4) & 1) * 8;
    const int bcol = (lane >> 3) & 1;

    #pragma unroll
    for (int s = 0; s < STAGES - 1; s++) {
        if (s < nk) load_stage(s, s);
        CP_COMMIT();
    }

    for (int i = 0; i < nk; i++) {
        CP_WAIT(STAGES - 2);
        __syncthreads();
        int pf = i + STAGES - 1;
        if (pf < nk) load_stage(pf % STAGES, pf);
        CP_COMMIT();

        uint32_t sb = st + (i % STAGES) * STAGE_B;
        #pragma unroll
        for (int ks = 0; ks < 4; ks++) {
            uint32_t ah[4][4], bh[4];
            int ca = 2 * ks + acol;
            #pragma unroll
            for (int mt = 0; mt < 4; mt++) {
                int row = arow + mt * 16;
                uint32_t ad = sb + row * 128 + ((ca ^ (row & 7)) << 4);
                LDSM_X4(ah[mt][0], ah[mt][1], ah[mt][2], ah[mt][3], ad);
            }
            int cb = 2 * ks + bcol;
            {
                uint32_t bd = sb + A_TILE + brow * 128 + ((cb ^ (brow & 7)) << 4);
                LDSM_X4(bh[0], bh[1], bh[2], bh[3], bd);
            }
            #pragma unroll
            for (int mt = 0; mt < 4; mt++)
                #pragma unroll
                for (int nti = 0; nti < 2; nti++)
                    MMA_FP16(acc[mt][nti], ah[mt], bh[nti * 2], bh[nti * 2 + 1]);
        }
    }
    __syncthreads();

    // ---- epilogue ----
    if constexpr (EPI == 0) {
        #pragma unroll
        for (int mt = 0; mt < 4; mt++)
            #pragma unroll
            for (int nti = 0; nti < 2; nti++) {
                int gm = m0 + wm + mt * 16 + (lane >> 2);
                int gn = n0 + wn + nti * 8 + (lane & 3) * 2;
                *(float2*)&C[(size_t)gm * N + gn] =
                    make_float2(acc[mt][nti][0], acc[mt][nti][1]);
                *(float2*)&C[(size_t)(gm + 8) * N + gn] =
                    make_float2(acc[mt][nti][2], acc[mt][nti][3]);
            }
    } else {
        const int region = (n0 < D_MODEL) ? 0 : (n0 < D_MODEL + KV_DIM ? 1 : 2);
        #pragma unroll
        for (int mt = 0; mt < 4; mt++)
            #pragma unroll
            for (int nti = 0; nti < 2; nti++) {
                int gm = m0 + wm + mt * 16 + (lane >> 2);
                int gn = n0 + wn + nti * 8 + (lane & 3) * 2;
                #pragma unroll
                for (int rr = 0; rr < 2; rr++) {
                    int row = gm + rr * 8;
                    float v0 = acc[mt][nti][2*rr], v1 = acc[mt][nti][2*rr + 1];
                    if (region == 2) {
                        *(__half2*)&g_Vh[(size_t)row * KV_DIM + (gn - D_MODEL - KV_DIM)] =
                            __floats2half2_rn(v0, v1);
                    } else {
                        int s = row & (S_LEN - 1);
                        int p = (gn & 63) >> 1;
                        float c = g_cos[(s << 5) + p], sn = g_sin[(s << 5) + p];
                        float xr = v0 * c - v1 * sn;
                        float xi = v0 * sn + v1 * c;
                        if (region == 0) {
                            const float qs = 0.125f * 1.4426950408889634f;
                            xr *= qs; xi *= qs;
                            *(__half2*)&g_Qf[(size_t)row * D_MODEL + gn] =
                                __floats2half2_rn(xr, xi);
                        } else {
                            *(__half2*)&g_Kh[(size_t)row * KV_DIM + (gn - D_MODEL)] =
                                __floats2half2_rn(xr, xi);
                        }
                    }
                }
            }
    }
}

// ======================= flash attention: 128 threads, 64 q-rows ============
// Q (fp16, 8KB) | 2 stages of { K 8K | V 8K } = 40KB total. 4 CTAs/SM.
#define SQH 0
#define SST 8192
#define FSTG 16384

__global__ __launch_bounds__(128, 4) void flash_mma()
{
    extern __shared__ char smem_raw[];
    uint32_t raw = smem_u32(smem_raw);
    uint32_t sb = (raw + 1023u) & ~1023u;

    const int tid = threadIdx.x, lane = tid & 31, w = tid >> 5;
    const int qt = gridDim.x - 1 - blockIdx.x;
    const int h = blockIdx.y, b = blockIdx.z;
    const int kvh = h >> 2;
    const int wq0 = qt * 64 + w * 16;

    {
        const size_t qg = ((size_t)(b * S_LEN + qt * 64)) * D_MODEL + h * HD;
        #pragma unroll
        for (int it = 0; it < 4; it++) {
            int c = tid + it * 128;
            int r = c >> 3, ch = c & 7;
            uint32_t so = (uint32_t)(r * 128 + ((ch ^ (r & 7)) << 4));
            cpa16(sb + SQH + so, g_Qf + qg + (size_t)r * D_MODEL + ch * 8);
        }
    }
    CP_COMMIT();

    const int ldr = tid >> 3, ldc = tid & 7;

    auto load_kv = [&](int stage, int kb) {
        uint32_t ss = sb + SST + stage * FSTG;
        size_t kg = ((size_t)(b * S_LEN + kb * 64)) * KV_DIM + kvh * HD;
        #pragma unroll
        for (int it = 0; it < 4; it++) {
            int r = ldr + it * 16;
            uint32_t so = (uint32_t)(r * 128 + ((ldc ^ (r & 7)) << 4));
            size_t go = kg + (size_t)r * KV_DIM + ldc * 8;
            cpa16(ss + so,        g_Kh + go);
            cpa16(ss + 8192 + so, g_Vh + go);
        }
        CP_COMMIT();
    };

    load_kv(0, 0);
    CP_WAIT(1);
    __syncthreads();

    uint32_t qh[4][4];
    {
        int row = w * 16 + (lane & 15);
        int rb = row * 128;
        #pragma unroll
        for (int kf = 0; kf < 4; kf++) {
            int ch = kf * 2 + (lane >> 4);
            uint32_t off = (uint32_t)(rb + ((ch ^ (row & 7)) << 4));
            LDSM_X4(qh[kf][0], qh[kf][1], qh[kf][2], qh[kf][3], sb + SQH + off);
        }
    }

    float o[8][4];
    #pragma unroll
    for (int i = 0; i < 8; i++)
        #pragma unroll
        for (int j = 0; j < 4; j++) o[i][j] = 0.f;
    float m0 = -1e30f, m1 = -1e30f, l0 = 0.f, l1 = 0.f;

    const int brn = (lane & 7) + ((lane >> 4) & 1) * 8;
    const int bcc = (lane >> 3) & 1;
    const int vrb = (((lane >> 3) & 1) << 3) + (lane & 7);
    const int vcs = lane >> 4;
    const int nkb = qt + 1;

    for (int kb = 0; kb < nkb; kb++) {
        CP_WAIT(0);
        __syncthreads();
        if (kb + 1 < nkb) load_kv((kb + 1) & 1, kb + 1);

        uint32_t ks = sb + SST + (kb & 1) * FSTG;

        float s[8][4];
        #pragma unroll
        for (int i = 0; i < 8; i++)
            #pragma unroll
            for (int j = 0; j < 4; j++) s[i][j] = 0.f;

        #pragma unroll
        for (int kf = 0; kf < 4; kf++) {
            uint32_t bh[4][4];
            int ch = kf * 2 + bcc;
            #pragma unroll
            for (int np = 0; np < 4; np++) {
                int row = brn + np * 16;
                uint32_t off = (uint32_t)(row * 128 + ((ch ^ (row & 7)) << 4));
                LDSM_X4(bh[np][0], bh[np][1], bh[np][2], bh[np][3], ks + off);
            }
            #pragma unroll
            for (int nt = 0; nt < 8; nt++) {
                uint32_t b0 = bh[nt >> 1][(nt & 1) * 2];
                uint32_t b1 = bh[nt >> 1][(nt & 1) * 2 + 1];
                MMA_FP16(s[nt], qh[kf], b0, b1);
            }
        }

        int kbase = kb * 64;
        if (kbase + 63 > wq0) {
            int q0 = wq0 + (lane >> 2);
            int q1 = q0 + 8;
            #pragma unroll
            for (int nt = 0; nt < 8; nt++) {
                int k0 = kbase + nt * 8 + (lane & 3) * 2;
                if (k0     > q0) s[nt][0] = -1e30f;
                if (k0 + 1 > q0) s[nt][1] = -1e30f;
                if (k0     > q1) s[nt][2] = -1e30f;
                if (k0 + 1 > q1) s[nt][3] = -1e30f;
            }
        }

        // ---- running max (fp32, shfl) ----
        float mx0 = -1e30f, mx1 = -1e30f;
        #pragma unroll
        for (int nt = 0; nt < 8; nt++) {
            mx0 = fmaxf(mx0, fmaxf(s[nt][0], s[nt][1]));
            mx1 = fmaxf(mx1, fmaxf(s[nt][2], s[nt][3]));
        }
        mx0 = fmaxf(mx0, __shfl_xor_sync(0xffffffffu, mx0, 1));
        mx0 = fmaxf(mx0, __shfl_xor_sync(0xffffffffu, mx0, 2));
        mx1 = fmaxf(mx1, __shfl_xor_sync(0xffffffffu, mx1, 1));
        mx1 = fmaxf(mx1, __shfl_xor_sync(0xffffffffu, mx1, 2));
        float mn0 = fmaxf(m0, mx0), mn1 = fmaxf(m1, mx1);
        float a0 = exp2f(m0 - mn0), a1 = exp2f(m1 - mn1);
        m0 = mn0; m1 = mn1;

        // ---- P = ex2(s - m) in packed fp16 ----
        uint32_t ph[4][4];
        #pragma unroll
        for (int j = 0; j < 4; j++) {
            #pragma unroll
            for (int half = 0; half < 2; half++) {
                int nt = 2 * j + half;
                uint32_t u01, u23;
                PACK_HF2(u01, s[nt][0] - mn0, s[nt][1] - mn0);
                PACK_HF2(u23, s[nt][2] - mn1, s[nt][3] - mn1);
                EX2_HF2(u01);
                EX2_HF2(u23);
                ph[j][0 + 2*half] = u01;
                ph[j][1 + 2*half] = u23;
            }
        }

        // ---- row sums via HADD2 tree (off the tensor pipe) ----
        {
            __half2 t0 = __hadd2(__hadd2(uh2(ph[0][0]), uh2(ph[0][2])),
                                 __hadd2(uh2(ph[1][0]), uh2(ph[1][2])));
            __half2 t1 = __hadd2(__hadd2(uh2(ph[2][0]), uh2(ph[2][2])),
                                 __hadd2(uh2(ph[3][0]), uh2(ph[3][2])));
            __half2 tq0 = __hadd2(t0, t1);
            __half2 u0 = __hadd2(__hadd2(uh2(ph[0][1]), uh2(ph[0][3])),
                                 __hadd2(uh2(ph[1][1]), uh2(ph[1][3])));
            __half2 u1 = __hadd2(__hadd2(uh2(ph[2][1]), uh2(ph[2][3])),
                                 __hadd2(uh2(ph[3][1]), uh2(ph[3][3])));
            __half2 tq1 = __hadd2(u0, u1);
            float rs0 = __low2float(tq0) + __high2float(tq0);
            float rs1 = __low2float(tq1) + __high2float(tq1);
            rs0 += __shfl_xor_sync(0xffffffffu, rs0, 1);
            rs0 += __shfl_xor_sync(0xffffffffu, rs0, 2);
            rs1 += __shfl_xor_sync(0xffffffffu, rs1, 1);
            rs1 += __shfl_xor_sync(0xffffffffu, rs1, 2);
            l0 = l0 * a0 + rs0;
            l1 = l1 * a1 + rs1;
        }

        #pragma unroll
        for (int dt = 0; dt < 8; dt++) {
            o[dt][0] *= a0; o[dt][1] *= a0;
            o[dt][2] *= a1; o[dt][3] *= a1;
        }

        // ---- O += P V  (V [s][d], trans ldmatrix) ----
        uint32_t vs = ks + 8192;
        #pragma unroll
        for (int kf = 0; kf < 4; kf++) {
            int row = kf * 16 + vrb;
            uint32_t rowoff = (uint32_t)(row * 128);
            int rsw = row & 7;
            #pragma unroll
            for (int dp = 0; dp < 4; dp++) {
                int chunk = dp * 2 + vcs;
                uint32_t addr = vs + rowoff + (uint32_t)((chunk ^ rsw) << 4);
                uint32_t r0, r1, r2, r3;
                LDSM_X4T(r0, r1, r2, r3, addr);
                MMA_FP16(o[2*dp],     ph[kf], r0, r1);
                MMA_FP16(o[2*dp + 1], ph[kf], r2, r3);
            }
        }
    }

    // ---- epilogue: write O as fp16 (A operand of out-proj) ----
    float il0 = 1.0f / l0, il1 = 1.0f / l1;
    int q0 = wq0 + (lane >> 2);
    size_t ob = ((size_t)(b * S_LEN)) * D_MODEL + h * HD;
    #pragma unroll
    for (int dt = 0; dt < 8; dt++) {
        int d = dt * 8 + (lane & 3) * 2;
        #pragma unroll
        for (int rr = 0; rr < 2; rr++) {
            float v0 = o[dt][2*rr]     * (rr ? il1 : il0);
            float v1 = o[dt][2*rr + 1] * (rr ? il1 : il0);
            size_t off = ob + (size_t)(q0 + rr * 8) * D_MODEL + d;
            *(__half2*)&g_xh[off] = __floats2half2_rn(v0, v1);
        }
    }
}

// ======================= host launch =========================================
extern "C" void kernel_launch(void* const* d_in, const int* in_sizes, int n_in,
                              void* d_out, int out_size)
{
    const float* x  = (const float*)d_in[0];
    const float* wq = (const float*)d_in[2];
    const float* wk = (const float*)d_in[3];
    const float* wv = (const float*)d_in[4];
    const float* wo = (const float*)d_in[5];
    float* out = (float*)d_out;

    __half *xh, *whA, *who;
    cudaGetSymbolAddress((void**)&xh, g_xh);
    cudaGetSymbolAddress((void**)&whA, g_whA);
    cudaGetSymbolAddress((void**)&who, g_who);

    Freqs fr;
    for (int p = 0; p < 32; p++)
        fr.f[p] = (float)pow(10000.0, -(double)(2 * p) / 64.0);

    // (1) x -> fp16 + rope table
    int n4 = ROWS * D_MODEL / 4;
    split_kernel<<<(n4 + 255) / 256, 256>>>(x, n4, fr);
    // (2) all four weights transpose -> fp16
    splitT_all<<<dim3(NALLW / 32, D_MODEL / 32), dim3(32, 8)>>>(wq, wk, wv, wo);

    size_t shm = STAGES * STAGE_B + 1024;   // 74752
    cudaFuncSetAttribute(gemm_mma<0>, cudaFuncAttributeMaxDynamicSharedMemorySize, (int)shm);
    cudaFuncSetAttribute(gemm_mma<2>, cudaFuncAttributeMaxDynamicSharedMemorySize, (int)shm);

    // (3) merged QKV projection; Q rope+scale, K rope, V direct fp16
    gemm_mma<2><<<dim3(NQKV / BN, ROWS / BM), 256, shm>>>(
        xh, whA, nullptr, ROWS, NQKV, D_MODEL);

    // (4) flash attention: 128-thread CTAs, 64 q-rows, 4 CTAs/SM
    size_t fshm = SST + 2 * FSTG + 1024;   // 42240
    cudaFuncSetAttribute(flash_mma, cudaFuncAttributeMaxDynamicSharedMemorySize, (int)fshm);
    flash_mma<<<dim3(S_LEN / 64, NH, BATCH), 128, fshm>>>();

    // (5) out = O @ wo
    gemm_mma<0><<<dim3(D_MODEL / BN, ROWS / BM), 256, shm>>>(
        xh, who, out, ROWS, D_MODEL, D_MODEL);
}

// round 17
// speedup vs baseline: 1.0479x; 1.0479x over previous
#include <cuda_runtime.h>
#include <cuda_bf16.h>
#include <cuda_fp16.h>
#include <math.h>
#include <stdint.h>

#define S_LEN   2048
#define BATCH   2
#define D_MODEL 2048
#define KV_DIM  512
#define NH      32
#define NKV     8
#define HD      64
#define ROWS    (BATCH*S_LEN)   // 4096
#define NQKV    (D_MODEL + 2*KV_DIM)   // 3072
#define NALLW   (NQKV + D_MODEL)       // 5120

// ---------------- scratch (device globals; no allocation allowed) ----------
__device__ __half g_xh[ROWS*D_MODEL];        // x fp16 (later: O fp16)
__device__ __half g_whA[NQKV*D_MODEL];       // [wq;wk;wv]^T fp16
__device__ __half g_who[D_MODEL*D_MODEL];    // wo^T fp16
__device__ __half g_Qf[ROWS*D_MODEL];        // RoPE'd, 0.125*log2e-scaled fp16
__device__ __half g_Kh[ROWS*KV_DIM];         // RoPE'd K fp16 [token][kvdim]
__device__ __half g_Vh[ROWS*KV_DIM];         // V fp16 [token][kvdim]
__device__ float g_cos[S_LEN*32];
__device__ float g_sin[S_LEN*32];

// ======================= base-ISA PTX helpers ===============================
__device__ __forceinline__ uint32_t smem_u32(const void* p) {
    uint32_t a;
    asm("{ .reg .u64 t; cvta.to.shared.u64 t, %1; cvt.u32.u64 %0, t; }"
        : "=r"(a) : "l"(p));
    return a;
}
__device__ __forceinline__ void cpa16(uint32_t saddr, const void* g) {
    asm volatile("cp.async.cg.shared.global [%0], [%1], 16;" :: "r"(saddr), "l"(g));
}
#define CP_COMMIT() asm volatile("cp.async.commit_group;" ::: "memory")
#define CP_WAIT(n)  asm volatile("cp.async.wait_group %0;" :: "n"(n) : "memory")

#define LDSM_X4(r0, r1, r2, r3, a) \
    asm volatile("ldmatrix.sync.aligned.m8n8.x4.shared.b16 {%0,%1,%2,%3}, [%4];" \
        : "=r"(r0), "=r"(r1), "=r"(r2), "=r"(r3) : "r"(a))

#define LDSM_X4T(r0, r1, r2, r3, a) \
    asm volatile("ldmatrix.sync.aligned.m8n8.x4.trans.shared.b16 {%0,%1,%2,%3}, [%4];" \
        : "=r"(r0), "=r"(r1), "=r"(r2), "=r"(r3) : "r"(a))

#define MMA_FP16(d, a, b0, b1) \
    asm volatile("mma.sync.aligned.m16n8k16.row.col.f32.f16.f16.f32 " \
        "{%0,%1,%2,%3}, {%4,%5,%6,%7}, {%8,%9}, {%0,%1,%2,%3};" \
        : "+f"((d)[0]), "+f"((d)[1]), "+f"((d)[2]), "+f"((d)[3]) \
        : "r"((a)[0]), "r"((a)[1]), "r"((a)[2]), "r"((a)[3]), "r"(b0), "r"(b1))

#define PACK_HF2(d, lo, hi) \
    asm("cvt.rn.f16x2.f32 %0, %1, %2;" : "=r"(d) : "f"(hi), "f"(lo))

#define EX2_HF2(x) \
    asm("ex2.approx.f16x2 %0, %0;" : "+r"(x))

// ======================= precompute kernels =================================
struct Freqs { float f[32]; };

__global__ void split_kernel(const float* __restrict__ a, int n4, Freqs fr)
{
    int i = blockIdx.x * blockDim.x + threadIdx.x;
    if (i < S_LEN * 32) {
        int s = i >> 5, p = i & 31;
        float ang = (float)s * fr.f[p];
        float c, sn;
        sincosf(ang, &sn, &c);
        g_cos[i] = c;
        g_sin[i] = sn;
    }
    if (i >= n4) return;
    float4 v = ((const float4*)a)[i];
    ((__half2*)g_xh)[2*i]   = __floats2half2_rn(v.x, v.y);
    ((__half2*)g_xh)[2*i+1] = __floats2half2_rn(v.z, v.w);
}

// ALL FOUR weights -> transposed fp16
__global__ void splitT_all(const float* __restrict__ wq,
                           const float* __restrict__ wk,
                           const float* __restrict__ wv,
                           const float* __restrict__ wo)
{
    __shared__ float t[32][33];
    int n0 = blockIdx.x * 32, k0 = blockIdx.y * 32;
    const float* w;
    int Nd, c0;
    __half* dst;
    int drow;
    if (n0 < D_MODEL)                 { w = wq; Nd = D_MODEL; c0 = n0;                    dst = g_whA; drow = n0; }
    else if (n0 < D_MODEL + KV_DIM)   { w = wk; Nd = KV_DIM;  c0 = n0 - D_MODEL;          dst = g_whA; drow = n0; }
    else if (n0 < NQKV)               { w = wv; Nd = KV_DIM;  c0 = n0 - D_MODEL - KV_DIM; dst = g_whA; drow = n0; }
    else                              { w = wo; Nd = D_MODEL; c0 = n0 - NQKV;             dst = g_who; drow = n0 - NQKV; }
    for (int r = threadIdx.y; r < 32; r += 8)
        t[r][threadIdx.x] = w[(size_t)(k0 + r) * Nd + c0 + threadIdx.x];
    __syncthreads();
    for (int r = threadIdx.y; r < 32; r += 8)
        dst[(size_t)(drow + r) * D_MODEL + k0 + threadIdx.x] =
            __float2half_rn(t[threadIdx.x][r]);
}

// ======================= fp16 mma.sync GEMM, BK=64 (R15 proven) =============
#define BM 128
#define BN 128
#define BK 64
#define STAGES 3
#define TILE_B  (BM*BK*2)        // 16384 B
#define STAGE_B (2*TILE_B)       // 32768 B : A | B

template<int EPI>
__global__ __launch_bounds__(256, 2) void gemm_mma(
    const __half* __restrict__ Ah, const __half* __restrict__ Bh,
    float* __restrict__ C, int M, int N, int K)
{
    extern __shared__ char smem_raw[];
    const int tid  = threadIdx.x;
    const int wid  = tid >> 5;
    const int lane = tid & 31;
    const int m0 = blockIdx.y * BM, n0 = blockIdx.x * BN;
    const int wm = (wid >> 2) * 64;
    const int wn = (wid & 3) * 32;
    const int nk = K / BK;

    uint32_t raw = smem_u32(smem_raw);
    uint32_t st  = (raw + 1023u) & ~1023u;

    const __half* gA_h = Ah + (size_t)m0 * K;
    const __half* gB_h = Bh + (size_t)n0 * K;

    const int lr = tid >> 3, lc = tid & 7;

    auto load_stage = [&](int s, int j) {
        uint32_t sb = st + s * STAGE_B;
        size_t kk = (size_t)j * BK;
        #pragma unroll
        for (int it = 0; it < 4; it++) {
            int r = lr + it * 32;
            uint32_t so = (uint32_t)(r * 128 + ((lc ^ (r & 7)) << 4));
            size_t go = kk + (size_t)r * K + lc * 8;
            cpa16(sb + so,          gA_h + go);
            cpa16(sb + TILE_B + so, gB_h + go);
        }
    };

    float acc[4][4][4];
    #pragma unroll
    for (int i = 0; i < 4; i++)
        #pragma unroll
        for (int j = 0; j < 4; j++)
            #pragma unroll
            for (int k = 0; k < 4; k++) acc[i][j][k] = 0.f;

    const int arow = wm + (lane & 15);
    const int acol = (lane >> 4);
    const int brow = wn + (lane & 7) + ((lane >> 4) & 1) * 8;
    const int bcol = (lane >> 3) & 1;

    #pragma unroll
    for (int s = 0; s < STAGES - 1; s++) {
        if (s < nk) load_stage(s, s);
        CP_COMMIT();
    }

    for (int i = 0; i < nk; i++) {
        CP_WAIT(STAGES - 2);
        __syncthreads();
        int pf = i + STAGES - 1;
        if (pf < nk) load_stage(pf % STAGES, pf);
        CP_COMMIT();

        uint32_t sb = st + (i % STAGES) * STAGE_B;
        #pragma unroll
        for (int ks = 0; ks < 4; ks++) {
            uint32_t ah[4][4], bh[2][4];
            int ca = 2 * ks + acol;
            #pragma unroll
            for (int mt = 0; mt < 4; mt++) {
                int row = arow + mt * 16;
                uint32_t ad = sb + row * 128 + ((ca ^ (row & 7)) << 4);
                LDSM_X4(ah[mt][0], ah[mt][1], ah[mt][2], ah[mt][3], ad);
            }
            int cb = 2 * ks + bcol;
            #pragma unroll
            for (int nt = 0; nt < 2; nt++) {
                int row = brow + nt * 16;
                uint32_t bd = sb + TILE_B + row * 128 + ((cb ^ (row & 7)) << 4);
                LDSM_X4(bh[nt][0], bh[nt][1], bh[nt][2], bh[nt][3], bd);
            }
            #pragma unroll
            for (int mt = 0; mt < 4; mt++)
                #pragma unroll
                for (int nti = 0; nti < 4; nti++) {
                    uint32_t b0 = bh[nti >> 1][(nti & 1) * 2];
                    uint32_t b1 = bh[nti >> 1][(nti & 1) * 2 + 1];
                    MMA_FP16(acc[mt][nti], ah[mt], b0, b1);
                }
        }
    }
    __syncthreads();

    // ---- epilogue ----
    if constexpr (EPI == 0) {
        #pragma unroll
        for (int mt = 0; mt < 4; mt++)
            #pragma unroll
            for (int nti = 0; nti < 4; nti++) {
                int gm = m0 + wm + mt * 16 + (lane >> 2);
                int gn = n0 + wn + nti * 8 + (lane & 3) * 2;
                *(float2*)&C[(size_t)gm * N + gn] =
                    make_float2(acc[mt][nti][0], acc[mt][nti][1]);
                *(float2*)&C[(size_t)(gm + 8) * N + gn] =
                    make_float2(acc[mt][nti][2], acc[mt][nti][3]);
            }
    } else {
        const int region = (n0 < D_MODEL) ? 0 : (n0 < D_MODEL + KV_DIM ? 1 : 2);
        #pragma unroll
        for (int mt = 0; mt < 4; mt++)
            #pragma unroll
            for (int nti = 0; nti < 4; nti++) {
                int gm = m0 + wm + mt * 16 + (lane >> 2);
                int gn = n0 + wn + nti * 8 + (lane & 3) * 2;
                #pragma unroll
                for (int rr = 0; rr < 2; rr++) {
                    int row = gm + rr * 8;
                    float v0 = acc[mt][nti][2*rr], v1 = acc[mt][nti][2*rr + 1];
                    if (region == 2) {
                        *(__half2*)&g_Vh[(size_t)row * KV_DIM + (gn - D_MODEL - KV_DIM)] =
                            __floats2half2_rn(v0, v1);
                    } else {
                        int s = row & (S_LEN - 1);
                        int p = (gn & 63) >> 1;
                        float c = g_cos[(s << 5) + p], sn = g_sin[(s << 5) + p];
                        float xr = v0 * c - v1 * sn;
                        float xi = v0 * sn + v1 * c;
                        if (region == 0) {
                            const float qs = 0.125f * 1.4426950408889634f;
                            xr *= qs; xi *= qs;
                            *(__half2*)&g_Qf[(size_t)row * D_MODEL + gn] =
                                __floats2half2_rn(xr, xi);
                        } else {
                            *(__half2*)&g_Kh[(size_t)row * KV_DIM + (gn - D_MODEL)] =
                                __floats2half2_rn(xr, xi);
                        }
                    }
                }
            }
    }
}

// ======================= flash attention: 128 thr, 64 q-rows, 3-stage KV ====
// Q (fp16, 8KB) | 3 stages of { K 8K | V 8K } = 56KB total. 4 CTAs/SM.
#define SQH 0
#define SST 8192
#define FSTG 16384
#define FKSTG 3
#define HONE 0x3C003C00u   // fp16x2 {1.0, 1.0}

__global__ __launch_bounds__(128, 4) void flash_mma()
{
    extern __shared__ char smem_raw[];
    uint32_t raw = smem_u32(smem_raw);
    uint32_t sb = (raw + 1023u) & ~1023u;

    const int tid = threadIdx.x, lane = tid & 31, w = tid >> 5;
    const int qt = gridDim.x - 1 - blockIdx.x;
    const int h = blockIdx.y, b = blockIdx.z;
    const int kvh = h >> 2;
    const int wq0 = qt * 64 + w * 16;

    // ---- Q tile load (its own group) ----
    {
        const size_t qg = ((size_t)(b * S_LEN + qt * 64)) * D_MODEL + h * HD;
        #pragma unroll
        for (int it = 0; it < 4; it++) {
            int c = tid + it * 128;
            int r = c >> 3, ch = c & 7;
            uint32_t so = (uint32_t)(r * 128 + ((ch ^ (r & 7)) << 4));
            cpa16(sb + SQH + so, g_Qf + qg + (size_t)r * D_MODEL + ch * 8);
        }
    }
    CP_COMMIT();

    const int ldr = tid >> 3, ldc = tid & 7;

    auto load_kv = [&](int stage, int kb) {
        uint32_t ss = sb + SST + stage * FSTG;
        size_t kg = ((size_t)(b * S_LEN + kb * 64)) * KV_DIM + kvh * HD;
        #pragma unroll
        for (int it = 0; it < 4; it++) {
            int r = ldr + it * 16;
            uint32_t so = (uint32_t)(r * 128 + ((ldc ^ (r & 7)) << 4));
            size_t go = kg + (size_t)r * KV_DIM + ldc * 8;
            cpa16(ss + so,        g_Kh + go);
            cpa16(ss + 8192 + so, g_Vh + go);
        }
        CP_COMMIT();
    };

    const int nkb = qt + 1;
    // prefill 2 KV stages (or 1 if only 1 tile)
    load_kv(0, 0);
    if (nkb > 1) load_kv(1, 1);
    else         CP_COMMIT();     // keep group accounting uniform

    // wait for Q (3 groups outstanding at most: Q, kv0, kv1 -> Q done when <=2 left)
    CP_WAIT(2);
    __syncthreads();

    uint32_t qh[4][4];
    {
        int row = w * 16 + (lane & 15);
        int rb = row * 128;
        #pragma unroll
        for (int kf = 0; kf < 4; kf++) {
            int ch = kf * 2 + (lane >> 4);
            uint32_t off = (uint32_t)(rb + ((ch ^ (row & 7)) << 4));
            LDSM_X4(qh[kf][0], qh[kf][1], qh[kf][2], qh[kf][3], sb + SQH + off);
        }
    }

    float o[8][4];
    #pragma unroll
    for (int i = 0; i < 8; i++)
        #pragma unroll
        for (int j = 0; j < 4; j++) o[i][j] = 0.f;
    float m0 = -1e30f, m1 = -1e30f, l0 = 0.f, l1 = 0.f;

    const int brn = (lane & 7) + ((lane >> 4) & 1) * 8;
    const int bcc = (lane >> 3) & 1;
    const int vrb = (((lane >> 3) & 1) << 3) + (lane & 7);
    const int vcs = lane >> 4;

    for (int kb = 0; kb < nkb; kb++) {
        // current tile resident when at most 1 newer group is in flight
        CP_WAIT(1);
        __syncthreads();
        if (kb + 2 < nkb) load_kv((kb + 2) % FKSTG, kb + 2);
        else              CP_COMMIT();   // keep group count consistent

        uint32_t ks = sb + SST + (kb % FKSTG) * FSTG;

        float s[8][4];
        #pragma unroll
        for (int i = 0; i < 8; i++)
            #pragma unroll
            for (int j = 0; j < 4; j++) s[i][j] = 0.f;

        #pragma unroll
        for (int kf = 0; kf < 4; kf++) {
            uint32_t bh[4][4];
            int ch = kf * 2 + bcc;
            #pragma unroll
            for (int np = 0; np < 4; np++) {
                int row = brn + np * 16;
                uint32_t off = (uint32_t)(row * 128 + ((ch ^ (row & 7)) << 4));
                LDSM_X4(bh[np][0], bh[np][1], bh[np][2], bh[np][3], ks + off);
            }
            #pragma unroll
            for (int nt = 0; nt < 8; nt++) {
                uint32_t b0 = bh[nt >> 1][(nt & 1) * 2];
                uint32_t b1 = bh[nt >> 1][(nt & 1) * 2 + 1];
                MMA_FP16(s[nt], qh[kf], b0, b1);
            }
        }

        int kbase = kb * 64;
        if (kbase + 63 > wq0) {
            int q0 = wq0 + (lane >> 2);
            int q1 = q0 + 8;
            #pragma unroll
            for (int nt = 0; nt < 8; nt++) {
                int k0 = kbase + nt * 8 + (lane & 3) * 2;
                if (k0     > q0) s[nt][0] = -1e30f;
                if (k0 + 1 > q0) s[nt][1] = -1e30f;
                if (k0     > q1) s[nt][2] = -1e30f;
                if (k0 + 1 > q1) s[nt][3] = -1e30f;
            }
        }

        // ---- running max (fp32, shfl) ----
        float mx0 = -1e30f, mx1 = -1e30f;
        #pragma unroll
        for (int nt = 0; nt < 8; nt++) {
            mx0 = fmaxf(mx0, fmaxf(s[nt][0], s[nt][1]));
            mx1 = fmaxf(mx1, fmaxf(s[nt][2], s[nt][3]));
        }
        mx0 = fmaxf(mx0, __shfl_xor_sync(0xffffffffu, mx0, 1));
        mx0 = fmaxf(mx0, __shfl_xor_sync(0xffffffffu, mx0, 2));
        mx1 = fmaxf(mx1, __shfl_xor_sync(0xffffffffu, mx1, 1));
        mx1 = fmaxf(mx1, __shfl_xor_sync(0xffffffffu, mx1, 2));
        float mn0 = fmaxf(m0, mx0), mn1 = fmaxf(m1, mx1);
        float a0 = exp2f(m0 - mn0), a1 = exp2f(m1 - mn1);
        m0 = mn0; m1 = mn1;

        // ---- P = ex2(s - m) in packed fp16 ----
        uint32_t ph[4][4];
        #pragma unroll
        for (int j = 0; j < 4; j++) {
            #pragma unroll
            for (int half = 0; half < 2; half++) {
                int nt = 2 * j + half;
                uint32_t u01, u23;
                PACK_HF2(u01, s[nt][0] - mn0, s[nt][1] - mn0);
                PACK_HF2(u23, s[nt][2] - mn1, s[nt][3] - mn1);
                EX2_HF2(u01);
                EX2_HF2(u23);
                ph[j][0 + 2*half] = u01;
                ph[j][1 + 2*half] = u23;
            }
        }

        // ---- row sums via ones-B MMA (R15 proven) ----
        float rsum[4] = {0.f, 0.f, 0.f, 0.f};
        #pragma unroll
        for (int kf = 0; kf < 4; kf++)
            MMA_FP16(rsum, ph[kf], HONE, HONE);
        l0 = l0 * a0 + rsum[0];
        l1 = l1 * a1 + rsum[2];

        #pragma unroll
        for (int dt = 0; dt < 8; dt++) {
            o[dt][0] *= a0; o[dt][1] *= a0;
            o[dt][2] *= a1; o[dt][3] *= a1;
        }

        // ---- O += P V  (V [s][d], trans ldmatrix) ----
        uint32_t vs = ks + 8192;
        #pragma unroll
        for (int kf = 0; kf < 4; kf++) {
            int row = kf * 16 + vrb;
            uint32_t rowoff = (uint32_t)(row * 128);
            int rsw = row & 7;
            #pragma unroll
            for (int dp = 0; dp < 4; dp++) {
                int chunk = dp * 2 + vcs;
                uint32_t addr = vs + rowoff + (uint32_t)((chunk ^ rsw) << 4);
                uint32_t r0, r1, r2, r3;
                LDSM_X4T(r0, r1, r2, r3, addr);
                MMA_FP16(o[2*dp],     ph[kf], r0, r1);
                MMA_FP16(o[2*dp + 1], ph[kf], r2, r3);
            }
        }
    }

    // ---- epilogue: write O as fp16 (A operand of out-proj) ----
    float il0 = 1.0f / l0, il1 = 1.0f / l1;
    int q0 = wq0 + (lane >> 2);
    size_t ob = ((size_t)(b * S_LEN)) * D_MODEL + h * HD;
    #pragma unroll
    for (int dt = 0; dt < 8; dt++) {
        int d = dt * 8 + (lane & 3) * 2;
        #pragma unroll
        for (int rr = 0; rr < 2; rr++) {
            float v0 = o[dt][2*rr]     * (rr ? il1 : il0);
            float v1 = o[dt][2*rr + 1] * (rr ? il1 : il0);
            size_t off = ob + (size_t)(q0 + rr * 8) * D_MODEL + d;
            *(__half2*)&g_xh[off] = __floats2half2_rn(v0, v1);
        }
    }
}

// ======================= host launch =========================================
extern "C" void kernel_launch(void* const* d_in, const int* in_sizes, int n_in,
                              void* d_out, int out_size)
{
    const float* x  = (const float*)d_in[0];
    const float* wq = (const float*)d_in[2];
    const float* wk = (const float*)d_in[3];
    const float* wv = (const float*)d_in[4];
    const float* wo = (const float*)d_in[5];
    float* out = (float*)d_out;

    __half *xh, *whA, *who;
    cudaGetSymbolAddress((void**)&xh, g_xh);
    cudaGetSymbolAddress((void**)&whA, g_whA);
    cudaGetSymbolAddress((void**)&who, g_who);

    Freqs fr;
    for (int p = 0; p < 32; p++)
        fr.f[p] = (float)pow(10000.0, -(double)(2 * p) / 64.0);

    // (1) x -> fp16 + rope table
    int n4 = ROWS * D_MODEL / 4;
    split_kernel<<<(n4 + 255) / 256, 256>>>(x, n4, fr);
    // (2) all four weights transpose -> fp16
    splitT_all<<<dim3(NALLW / 32, D_MODEL / 32), dim3(32, 8)>>>(wq, wk, wv, wo);

    size_t shm = STAGES * STAGE_B + 1024;   // 99328
    cudaFuncSetAttribute(gemm_mma<0>, cudaFuncAttributeMaxDynamicSharedMemorySize, (int)shm);
    cudaFuncSetAttribute(gemm_mma<2>, cudaFuncAttributeMaxDynamicSharedMemorySize, (int)shm);

    // (3) merged QKV projection; Q rope+scale, K rope, V direct fp16
    gemm_mma<2><<<dim3(NQKV / BN, ROWS / BM), 256, shm>>>(
        xh, whA, nullptr, ROWS, NQKV, D_MODEL);

    // (4) flash attention: 128-thread CTAs, 64 q-rows, 3-stage KV, 4 CTAs/SM
    size_t fshm = SST + FKSTG * FSTG + 1024;   // 58624
    cudaFuncSetAttribute(flash_mma, cudaFuncAttributeMaxDynamicSharedMemorySize, (int)fshm);
    flash_mma<<<dim3(S_LEN / 64, NH, BATCH), 128, fshm>>>();

    // (5) out = O @ wo
    gemm_mma<0><<<dim3(D_MODEL / BN, ROWS / BM), 256, shm>>>(
        xh, who, out, ROWS, D_MODEL, D_MODEL);
}